// round 1
// baseline (speedup 1.0000x reference)
#include <cuda_runtime.h>
#include <cuda_bf16.h>

// Problem constants (fixed by the reference)
#define NW        4          // N_WINDOWS
#define CCH       32         // N_MASKS
#define MPW       8          // masks per window
#define IMG_H     1024
#define IMG_W     1024
#define HW        (IMG_H * IMG_W)
#define WIN_H     512
#define WIN_W     512
#define SLOT_DIM  64
#define SIM_THRESH 0.1f
#define P_MAX     304        // max candidate pairs (<= 6 adjacencies * 49)

// Scratch (device globals; no allocation allowed)
__device__ unsigned d_edge_parts[NW][4];   // [window][L,R,T,B] bitmask over absolute channel id
__device__ int      d_map[CCH];            // final channel remap

// ---------------------------------------------------------------------------
// Kernel A: per (window, edge) block computes the set of channels (within the
// window's channel range) that appear as argmax along that edge. No atomics,
// unconditional overwrite of d_edge_parts -> no zero-init kernel needed.
// ---------------------------------------------------------------------------
__global__ void __launch_bounds__(512) edge_kernel(
    const float* __restrict__ masks,
    const int* __restrict__ pad_left,
    const int* __restrict__ pad_top)
{
    int w = blockIdx.x >> 2;     // window
    int e = blockIdx.x & 3;      // 0=L 1=R 2=T 3=B

    int pl = pad_left[w], pt = pad_top[w];
    int ys = max(pt, 0), ye = min(pt + WIN_H, IMG_H);
    int xs = max(pl, 0), xe = min(pl + WIN_W, IMG_W);

    unsigned mybit = 0u;
    if (ys < ye && xs < xe) {
        int len = (e < 2) ? (ye - ys) : (xe - xs);
        int t = threadIdx.x;
        if (t < len) {
            int y, x;
            if      (e == 0) { y = ys + t; x = xs;     }
            else if (e == 1) { y = ys + t; x = xe - 1; }
            else if (e == 2) { y = ys;     x = xs + t; }
            else             { y = ye - 1; x = xs + t; }
            const float* p = masks + (long long)y * IMG_W + x;
            float best = p[0];
            int id = 0;
            #pragma unroll
            for (int c = 1; c < CCH; c++) {
                float v = p[(long long)c * HW];
                if (v > best) { best = v; id = c; }
            }
            if (id >= w * MPW && id < (w + 1) * MPW) mybit = 1u << id;
        }
    }

    unsigned wm = __reduce_or_sync(0xffffffffu, mybit);
    __shared__ unsigned sm[16];
    if ((threadIdx.x & 31) == 0) sm[threadIdx.x >> 5] = wm;
    __syncthreads();
    if (threadIdx.x == 0) {
        unsigned acc = 0;
        #pragma unroll
        for (int i = 0; i < 16; i++) acc |= sm[i];
        d_edge_parts[w][e] = acc;
    }
}

// ---------------------------------------------------------------------------
// Kernel B: one block. Builds adjacency + candidate pair list from pad arrays,
// computes cosine similarities in parallel, then thread 0 runs the sequential
// merge scan and emits the 32-entry channel remap table.
// ---------------------------------------------------------------------------
__global__ void __launch_bounds__(256) map_kernel(
    const float* __restrict__ sf,       // (NW, MPW-1, SLOT_DIM)
    const int* __restrict__ pad_left,
    const int* __restrict__ pad_top)
{
    __shared__ int  s_ci[P_MAX];
    __shared__ int  s_cj[P_MAX];
    __shared__ char s_hz[P_MAX];
    __shared__ char s_pass[P_MAX];
    __shared__ int  s_P;

    if (threadIdx.x == 0) {
        int pl[NW], pt[NW];
        for (int i = 0; i < NW; i++) { pl[i] = pad_left[i]; pt[i] = pad_top[i]; }

        int na = 0;
        int ai[12], aj[12]; char ah[12];
        for (int i = 0; i < NW; i++) {
            for (int j = i + 1; j < NW; j++) {
                if (pt[i] == pt[j] && abs(pl[i] - pl[j]) == WIN_W) {
                    if (pl[i] < pl[j]) { ai[na] = i; aj[na] = j; }
                    else               { ai[na] = j; aj[na] = i; }
                    ah[na] = 1; na++;
                }
                if (pl[i] == pl[j] && abs(pt[i] - pt[j]) == WIN_H) {
                    if (pt[i] < pt[j]) { ai[na] = i; aj[na] = j; }
                    else               { ai[na] = j; aj[na] = i; }
                    ah[na] = 0; na++;
                }
            }
        }
        int P = 0;
        for (int a = 0; a < na; a++) {
            int si = ai[a] * MPW, sj = aj[a] * MPW;
            for (int ci = si + 1; ci < si + MPW; ci++)
                for (int cj = sj + 1; cj < sj + MPW; cj++) {
                    s_ci[P] = ci; s_cj[P] = cj; s_hz[P] = ah[a]; P++;
                }
        }
        s_P = P;
    }
    __syncthreads();

    int P = s_P;
    for (int p = threadIdx.x; p < P; p += blockDim.x) {
        int ci = s_ci[p], cj = s_cj[p];
        int wi = ci / MPW, wj = cj / MPW;
        int ri = ci % MPW - 1, rj = cj % MPW - 1;
        const float* fi = sf + ((long long)wi * (MPW - 1) + ri) * SLOT_DIM;
        const float* fj = sf + ((long long)wj * (MPW - 1) + rj) * SLOT_DIM;
        float dot = 0.f, ni = 0.f, nj = 0.f;
        #pragma unroll
        for (int k = 0; k < SLOT_DIM; k++) {
            float a = fi[k], b = fj[k];
            dot += a * b; ni += a * a; nj += b * b;
        }
        float sim = dot / ((sqrtf(ni) + 1e-8f) * (sqrtf(nj) + 1e-8f));

        bool ok;
        if (s_hz[p]) {
            ok = ((d_edge_parts[wi][1] >> ci) & 1u) && ((d_edge_parts[wj][0] >> cj) & 1u);
        } else {
            ok = ((d_edge_parts[wi][3] >> ci) & 1u) && ((d_edge_parts[wj][2] >> cj) & 1u);
        }
        s_pass[p] = (ok && sim > SIM_THRESH) ? 1 : 0;
    }
    __syncthreads();

    if (threadIdx.x == 0) {
        int mp[CCH];
        bool merged[CCH];
        for (int c = 0; c < CCH; c++) { mp[c] = c; merged[c] = false; }
        for (int p = 0; p < P; p++) {
            int ci = s_ci[p], cj = s_cj[p];
            if (s_pass[p] && !merged[ci] && !merged[cj]) {
                int keep = min(ci, cj), rem = max(ci, cj);
                // move everything currently living in `rem` into `keep`
                for (int c = 0; c < CCH; c++)
                    if (mp[c] == rem) mp[c] = keep;
                merged[rem] = true;
            }
        }
        for (int c = 0; c < CCH; c++) d_map[c] = mp[c];
    }
}

// ---------------------------------------------------------------------------
// Kernel C: the heavy pass. Each thread owns 4 pixels (float4). Reads all 32
// channel planes (31 independent loads -> deep MLP), per-lane argmax with
// first-max-wins semantics, remap via d_map, writes remapped one-hot.
// ---------------------------------------------------------------------------
__global__ void __launch_bounds__(256) main_kernel(
    const float* __restrict__ masks,
    float* __restrict__ out)
{
    __shared__ int smap[CCH];
    if (threadIdx.x < CCH) smap[threadIdx.x] = d_map[threadIdx.x];
    __syncthreads();

    int idx = blockIdx.x * blockDim.x + threadIdx.x;   // float4 index, HW/4 total
    const float4* m4 = (const float4*)masks;
    float4* o4 = (float4*)out;
    const int stride4 = HW / 4;

    float4 v = m4[idx];
    float b0 = v.x, b1 = v.y, b2 = v.z, b3 = v.w;
    int a0 = 0, a1 = 0, a2 = 0, a3 = 0;

    #pragma unroll
    for (int c = 1; c < CCH; c++) {
        float4 t = m4[(long long)c * stride4 + idx];
        if (t.x > b0) { b0 = t.x; a0 = c; }
        if (t.y > b1) { b1 = t.y; a1 = c; }
        if (t.z > b2) { b2 = t.z; a2 = c; }
        if (t.w > b3) { b3 = t.w; a3 = c; }
    }

    a0 = smap[a0]; a1 = smap[a1]; a2 = smap[a2]; a3 = smap[a3];

    #pragma unroll
    for (int c = 0; c < CCH; c++) {
        float4 o;
        o.x = (a0 == c) ? 1.0f : 0.0f;
        o.y = (a1 == c) ? 1.0f : 0.0f;
        o.z = (a2 == c) ? 1.0f : 0.0f;
        o.w = (a3 == c) ? 1.0f : 0.0f;
        o4[(long long)c * stride4 + idx] = o;
    }
}

// ---------------------------------------------------------------------------
extern "C" void kernel_launch(void* const* d_in, const int* in_sizes, int n_in,
                              void* d_out, int out_size)
{
    const float* masks = (const float*)d_in[0];
    const float* sf    = (const float*)d_in[1];
    const int*   pl    = (const int*)d_in[2];
    const int*   pt    = (const int*)d_in[3];
    float*       out   = (float*)d_out;

    edge_kernel<<<NW * 4, 512>>>(masks, pl, pt);
    map_kernel<<<1, 256>>>(sf, pl, pt);
    main_kernel<<<HW / 4 / 256, 256>>>(masks, out);
}